// round 4
// baseline (speedup 1.0000x reference)
#include <cuda_runtime.h>
#include <math.h>
#include <stdint.h>

// Problem constants
#define NN 50000
#define NE 800000
#define NF 128
#define NH 128
#define NH2 64
#define NG 512

// ---------------- scratch (static device globals; no allocation) -------------
__device__ float d_g[(size_t)NN * NF];   // projected features (also reused 64-wide)
__device__ float d_h[(size_t)NN * NF];   // activations (also reused 64-wide)
__device__ float d_dinv[NN];
__device__ int   d_cnt[NN];
__device__ int   d_rowptr[NN + 1];
__device__ int   d_cursor[NN];
__device__ int   d_col[NE];
__device__ float d_pool[NG * NH2];
__device__ int   d_gcnt[NG];

// ---------------- init ------------------------------------------------------
__global__ void init_kernel() {
    int i = blockIdx.x * blockDim.x + threadIdx.x;
    if (i < NN) d_cnt[i] = 0;
    if (i < NG * NH2) d_pool[i] = 0.0f;
    if (i < NG) d_gcnt[i] = 0;
}

// ---------------- degree count: 4 edges/thread for MLP ----------------------
__global__ void count_kernel(const int* __restrict__ ei) {
    int e0 = (blockIdx.x * blockDim.x + threadIdx.x) * 4;
    if (e0 + 3 < NE) {
        int4 d4 = *(const int4*)&ei[NE + e0];
        atomicAdd(&d_cnt[d4.x], 1);
        atomicAdd(&d_cnt[d4.y], 1);
        atomicAdd(&d_cnt[d4.z], 1);
        atomicAdd(&d_cnt[d4.w], 1);
    } else if (e0 < NE) {
        for (int e = e0; e < NE; e++) atomicAdd(&d_cnt[ei[NE + e]], 1);
    }
}

// ---------------- single-block chunked scan (one barrier round) --------------
__global__ void scan_kernel() {
    const int C = (NN + 1023) / 1024;   // 49 elements per thread
    int tid = threadIdx.x, lane = tid & 31, wid = tid >> 5;
    int base = tid * C;
    int total = 0;
    #pragma unroll 7
    for (int j = 0; j < C; j++) {
        int i = base + j;
        if (i < NN) total += d_cnt[i];
    }
    // block exclusive scan of per-thread totals
    __shared__ int wsum[32];
    int x = total;
    #pragma unroll
    for (int o = 1; o < 32; o <<= 1) {
        int t = __shfl_up_sync(0xFFFFFFFFu, x, o);
        if (lane >= o) x += t;
    }
    if (lane == 31) wsum[wid] = x;
    __syncthreads();
    if (wid == 0) {
        int w = wsum[lane];
        #pragma unroll
        for (int o = 1; o < 32; o <<= 1) {
            int t = __shfl_up_sync(0xFFFFFFFFu, w, o);
            if (lane >= o) w += t;
        }
        wsum[lane] = w;
    }
    __syncthreads();
    int run = (wid > 0 ? wsum[wid - 1] : 0) + x - total;  // exclusive prefix
    #pragma unroll 7
    for (int j = 0; j < C; j++) {
        int i = base + j;
        if (i < NN) {
            int v = d_cnt[i];
            d_rowptr[i] = run;
            d_cursor[i] = run;
            d_dinv[i]   = rsqrtf((float)(v + 1));  // deg includes self-loop
            run += v;
        }
    }
    if (tid == 1023) d_rowptr[NN] = run;  // == NE
}

// ---------------- CSR fill: 4 edges/thread ----------------------------------
__global__ void fill_kernel(const int* __restrict__ ei) {
    int e0 = (blockIdx.x * blockDim.x + threadIdx.x) * 4;
    if (e0 + 3 < NE) {
        int4 s4 = *(const int4*)&ei[e0];
        int4 d4 = *(const int4*)&ei[NE + e0];
        int p0 = atomicAdd(&d_cursor[d4.x], 1);
        int p1 = atomicAdd(&d_cursor[d4.y], 1);
        int p2 = atomicAdd(&d_cursor[d4.z], 1);
        int p3 = atomicAdd(&d_cursor[d4.w], 1);
        d_col[p0] = s4.x;
        d_col[p1] = s4.y;
        d_col[p2] = s4.z;
        d_col[p3] = s4.w;
    } else if (e0 < NE) {
        for (int e = e0; e < NE; e++) {
            int p = atomicAdd(&d_cursor[ei[NE + e]], 1);
            d_col[p] = ei[e];
        }
    }
}

// ---------------- GEMM: d_g = A @ W  (plain, dinv applied in agg) ------------
template <int K, int N, int SRC>   // SRC 0: A = param (x), 1: A = d_h
__global__ void gemm_kernel(const float* __restrict__ Aparam,
                            const float* __restrict__ W, int M) {
    constexpr int TN = N / 16;
    __shared__ float As[8][128];
    __shared__ float Ws[8][N];
    const float* __restrict__ A = (SRC == 0) ? Aparam : d_h;

    int tid = threadIdx.x;
    int m0 = blockIdx.x * 128;
    int ty = tid >> 4, tx = tid & 15;
    int mb = ty * 8, nb = tx * TN;

    float acc[8][TN];
    #pragma unroll
    for (int i = 0; i < 8; i++)
        #pragma unroll
        for (int j = 0; j < TN; j++) acc[i][j] = 0.0f;

    int arow = tid >> 1;
    int ac = (tid & 1) * 4;
    bool aok = (m0 + arow) < M;
    const float* Ap = A + (size_t)(m0 + arow) * K + ac;

    for (int k0 = 0; k0 < K; k0 += 8) {
        float4 av = aok ? *(const float4*)(Ap + k0) : make_float4(0.f, 0.f, 0.f, 0.f);
        float4 wv = make_float4(0.f, 0.f, 0.f, 0.f);
        int wrow, wc;
        if (N == 128) {
            wrow = tid >> 5; wc = (tid & 31) * 4;
            wv = *(const float4*)&W[(k0 + wrow) * N + wc];
        } else {
            wrow = tid >> 4; wc = (tid & 15) * 4;
            if (tid < 128) wv = *(const float4*)&W[(k0 + wrow) * N + wc];
        }
        __syncthreads();
        As[ac + 0][arow] = av.x;
        As[ac + 1][arow] = av.y;
        As[ac + 2][arow] = av.z;
        As[ac + 3][arow] = av.w;
        if (N == 128 || tid < 128) *(float4*)&Ws[wrow][wc] = wv;
        __syncthreads();
        #pragma unroll
        for (int k = 0; k < 8; k++) {
            float a0[8];
            *(float4*)(a0)     = *(float4*)&As[k][mb];
            *(float4*)(a0 + 4) = *(float4*)&As[k][mb + 4];
            float b0[TN];
            #pragma unroll
            for (int j4 = 0; j4 < TN; j4 += 4)
                *(float4*)(b0 + j4) = *(float4*)&Ws[k][nb + j4];
            #pragma unroll
            for (int i = 0; i < 8; i++)
                #pragma unroll
                for (int j = 0; j < TN; j++)
                    acc[i][j] = fmaf(a0[i], b0[j], acc[i][j]);
        }
    }

    #pragma unroll
    for (int i = 0; i < 8; i++) {
        int row = m0 + mb + i;
        if (row < M) {
            #pragma unroll
            for (int j4 = 0; j4 < TN; j4 += 4)
                *(float4*)&d_g[(size_t)row * N + nb + j4] =
                    *(float4*)&acc[i][j4];
        }
    }
}

// ---------------- agg F=128: warp/node, float4 lanes, relu -> d_h -----------
// out[i] = relu( dinv[i] * ( dinv[i]*g[i] + sum_c dinv[c]*g[c] ) + b )
__global__ void agg128_kernel(const float* __restrict__ bias) {
    int warp = threadIdx.x >> 5, lane = threadIdx.x & 31;
    int i = blockIdx.x * 8 + warp;
    if (i >= NN) return;
    const float4* __restrict__ g4 = (const float4*)d_g;
    float di = d_dinv[i];
    float4 acc = g4[(size_t)i * 32 + lane];
    acc.x *= di; acc.y *= di; acc.z *= di; acc.w *= di;
    int s = d_rowptr[i], e = d_rowptr[i + 1];
    int k = s;
    for (; k + 8 <= e; k += 8) {
        #pragma unroll
        for (int j = 0; j < 8; j++) {
            int c = d_col[k + j];
            float w = d_dinv[c];
            float4 v = g4[(size_t)c * 32 + lane];
            acc.x = fmaf(w, v.x, acc.x);
            acc.y = fmaf(w, v.y, acc.y);
            acc.z = fmaf(w, v.z, acc.z);
            acc.w = fmaf(w, v.w, acc.w);
        }
    }
    for (; k < e; k++) {
        int c = d_col[k];
        float w = d_dinv[c];
        float4 v = g4[(size_t)c * 32 + lane];
        acc.x = fmaf(w, v.x, acc.x);
        acc.y = fmaf(w, v.y, acc.y);
        acc.z = fmaf(w, v.z, acc.z);
        acc.w = fmaf(w, v.w, acc.w);
    }
    float4 b4 = ((const float4*)bias)[lane];
    float4 r;
    r.x = fmaxf(fmaf(di, acc.x, b4.x), 0.0f);
    r.y = fmaxf(fmaf(di, acc.y, b4.y), 0.0f);
    r.z = fmaxf(fmaf(di, acc.z, b4.z), 0.0f);
    r.w = fmaxf(fmaf(di, acc.w, b4.w), 0.0f);
    ((float4*)d_h)[(size_t)i * 32 + lane] = r;
}

// ---------------- agg F=64: warp/node, float2 lanes --------------------------
// MODE 0: relu -> d_h ; MODE 2: no relu, fused pooling atomics
template <int MODE>
__global__ void agg64_kernel(const float* __restrict__ bias,
                             const int* __restrict__ batch) {
    int warp = threadIdx.x >> 5, lane = threadIdx.x & 31;
    int i = blockIdx.x * 8 + warp;
    if (i >= NN) return;
    const float2* __restrict__ g2 = (const float2*)d_g;
    float di = d_dinv[i];
    float2 acc = g2[(size_t)i * 32 + lane];
    acc.x *= di; acc.y *= di;
    int s = d_rowptr[i], e = d_rowptr[i + 1];
    int k = s;
    for (; k + 8 <= e; k += 8) {
        #pragma unroll
        for (int j = 0; j < 8; j++) {
            int c = d_col[k + j];
            float w = d_dinv[c];
            float2 v = g2[(size_t)c * 32 + lane];
            acc.x = fmaf(w, v.x, acc.x);
            acc.y = fmaf(w, v.y, acc.y);
        }
    }
    for (; k < e; k++) {
        int c = d_col[k];
        float w = d_dinv[c];
        float2 v = g2[(size_t)c * 32 + lane];
        acc.x = fmaf(w, v.x, acc.x);
        acc.y = fmaf(w, v.y, acc.y);
    }
    float2 b2 = ((const float2*)bias)[lane];
    float rx = fmaf(di, acc.x, b2.x);
    float ry = fmaf(di, acc.y, b2.y);
    if (MODE == 0) {
        float2 r; r.x = fmaxf(rx, 0.0f); r.y = fmaxf(ry, 0.0f);
        ((float2*)d_h)[(size_t)i * 32 + lane] = r;
    } else {
        int b = batch[i];
        atomicAdd(&d_pool[b * NH2 + lane * 2 + 0], rx);
        atomicAdd(&d_pool[b * NH2 + lane * 2 + 1], ry);
        if (lane == 0) atomicAdd(&d_gcnt[b], 1);
    }
}

// ---------------- final: sigmoid(mean) @ Wfc + bfc ---------------------------
__global__ void final_kernel(const float* __restrict__ Wfc,
                             const float* __restrict__ bfc,
                             float* __restrict__ out) {
    int gidx = blockIdx.x * (blockDim.x >> 5) + (threadIdx.x >> 5);
    int lane = threadIdx.x & 31;
    if (gidx >= NG) return;
    float cnt = fmaxf((float)d_gcnt[gidx], 1.0f);
    float s0 = d_pool[gidx * NH2 + lane];
    float s1 = d_pool[gidx * NH2 + 32 + lane];
    float z0 = 1.0f / (1.0f + expf(-s0 / cnt));
    float z1 = 1.0f / (1.0f + expf(-s1 / cnt));
    float p = z0 * Wfc[lane] + z1 * Wfc[lane + 32];
    #pragma unroll
    for (int o = 16; o > 0; o >>= 1) p += __shfl_down_sync(0xFFFFFFFFu, p, o);
    if (lane == 0) out[gidx] = p + bfc[0];
}

// ---------------- launch -----------------------------------------------------
extern "C" void kernel_launch(void* const* d_in, const int* in_sizes, int n_in,
                              void* d_out, int out_size) {
    const float* x     = (const float*)d_in[0];
    const int*   ei    = (const int*)d_in[1];
    const int*   batch = (const int*)d_in[2];
    const float* W1    = (const float*)d_in[3];
    const float* b1    = (const float*)d_in[4];
    const float* W2    = (const float*)d_in[5];
    const float* b2    = (const float*)d_in[6];
    const float* W3    = (const float*)d_in[7];
    const float* b3    = (const float*)d_in[8];
    const float* Wfc   = (const float*)d_in[9];
    const float* bfc   = (const float*)d_in[10];
    float* out = (float*)d_out;

    const int gemm_blocks = (NN + 127) / 128;       // 391
    const int agg_blocks  = (NN + 7) / 8;           // 6250
    const int edge4_blocks = (NE / 4 + 255) / 256;  // 782

    init_kernel<<<(NN + 255) / 256, 256>>>();
    count_kernel<<<edge4_blocks, 256>>>(ei);
    scan_kernel<<<1, 1024>>>();
    fill_kernel<<<edge4_blocks, 256>>>(ei);

    // layer 1: 128 -> 128, relu
    gemm_kernel<128, 128, 0><<<gemm_blocks, 256>>>(x, W1, NN);
    agg128_kernel<<<agg_blocks, 256>>>(b1);

    // layer 2: 128 -> 64, relu
    gemm_kernel<128, 64, 1><<<gemm_blocks, 256>>>(nullptr, W2, NN);
    agg64_kernel<0><<<agg_blocks, 256>>>(b2, batch);

    // layer 3: 64 -> 64, no relu, fused pooling
    gemm_kernel<64, 64, 1><<<gemm_blocks, 256>>>(nullptr, W3, NN);
    agg64_kernel<2><<<agg_blocks, 256>>>(b3, batch);

    final_kernel<<<(NG + 7) / 8, 256>>>(Wfc, bfc, out);
}